// round 7
// baseline (speedup 1.0000x reference)
#include <cuda_runtime.h>
#include <cuda_bf16.h>
#include <math.h>
#include <stdint.h>

#define SS 16
#define NN 4096
#define MM 128
#define DD 128
#define OO 128
#define PAD 129

__device__ float g_w[SS*OO*DD];
__device__ float g_klso[SS*OO];

// ---- smem layout (byte offsets; dynamic smem is 1024-aligned already) ----
#define OFF_A        0          // float A[128*129] = 66048 B
#define OFF_SB0      66560      // bf16 [128][40] = 10240 B  (hi)
#define OFF_SB1      76800      // (mid)
#define OFF_SB2      87040      // (lo)
#define OFF_SCRATCH  66560      // trsm scratch aliases SB0 (9792 B; disjoint in time)
#define OFF_SQLP     97280
#define OFF_LPM      97792
#define OFF_UTLV     98304
#define OFF_DINV     98816
#define OFF_QMU      99328
#define OFF_EPSV     99840
#define OFF_RED      100352
#define SMEM_DYN     100864

#define SB_STRIDE_B  80         // 40 bf16 per row (32 data + 8 pad); 16B-multiple

__device__ __forceinline__ uint32_t s2u(const void* p) {
    uint32_t a;
    asm("{ .reg .u64 t; cvta.to.shared.u64 t, %1; cvt.u32.u64 %0, t; }"
        : "=r"(a) : "l"(p));
    return a;
}

__device__ __forceinline__ void ldsm_x4(uint32_t addr, uint32_t& r0, uint32_t& r1,
                                        uint32_t& r2, uint32_t& r3) {
    asm volatile("ldmatrix.sync.aligned.m8n8.x4.shared.b16 {%0,%1,%2,%3}, [%4];"
                 : "=r"(r0), "=r"(r1), "=r"(r2), "=r"(r3) : "r"(addr));
}

__device__ __forceinline__ void mma16816(float& c0, float& c1, float& c2, float& c3,
                                         uint32_t a0, uint32_t a1, uint32_t a2, uint32_t a3,
                                         uint32_t b0, uint32_t b1) {
    asm volatile(
        "mma.sync.aligned.m16n8k16.row.col.f32.bf16.bf16.f32 "
        "{%0,%1,%2,%3}, {%4,%5,%6,%7}, {%8,%9}, {%0,%1,%2,%3};"
        : "+f"(c0), "+f"(c1), "+f"(c2), "+f"(c3)
        : "r"(a0), "r"(a1), "r"(a2), "r"(a3), "r"(b0), "r"(b1));
}

// ---- 16x16 warp Cholesky (lanes 0..15 of calling warp) ----
__device__ __forceinline__ void chol16_warp(float* A, float* dinv) {
    const int lane = threadIdx.x & 31;
    if (lane < 16) {
        float row[16], rawv[16];
#pragma unroll
        for (int k = 0; k < 16; k++) row[k] = A[lane*PAD + k];
#pragma unroll
        for (int j = 0; j < 16; j++) {
            float raw = __shfl_sync(0xFFFFu, row[j], j);
            rawv[j] = raw;
            float inv = __fdividef(1.0f, raw);
            float tj = row[j] * inv;
#pragma unroll
            for (int k = j + 1; k < 16; k++) {
                float rkj = __shfl_sync(0xFFFFu, row[j], k);
                row[k] = fmaf(-tj, rkj, row[k]);
            }
        }
        float rs[16];
#pragma unroll
        for (int j = 0; j < 16; j++) rs[j] = rsqrtf(rawv[j]);
#pragma unroll
        for (int k = 0; k < 16; k++) {
            float v = row[k];
            if (k < lane)  v = row[k] * rs[k];
            if (k == lane) v = rawv[k] * rs[k];
            A[lane*PAD + k] = v;
        }
        dinv[lane] = rs[lane];
    }
    __syncwarp();
}

__device__ __noinline__ void chol_blocked(float* A, float* dinv, int tid) {
    const int warp = tid >> 5;
    const int ty = tid >> 4, tx = tid & 15;
#pragma unroll
    for (int jb = 0; jb < 8; jb++) {
        if (warp == 0) chol16_warp(A + (jb*16)*PAD + jb*16, dinv + jb*16);
        __syncthreads();
        const int nrows = 112 - jb*16;
        if (tid < nrows) {
            const int i = jb*16 + 16 + tid;
            const float* Ld = A + (jb*16)*PAD + jb*16;
            float* Ai = A + i*PAD + jb*16;
            float dv[16], t[16];
#pragma unroll
            for (int j = 0; j < 16; j++) dv[j] = dinv[jb*16 + j];
#pragma unroll
            for (int j = 0; j < 16; j++) t[j] = Ai[j];
#pragma unroll
            for (int j = 0; j < 16; j++) {
                float v = t[j] * dv[j];
                t[j] = v;
#pragma unroll
                for (int k = j + 1; k < 16; k++)
                    t[k] = fmaf(-v, Ld[k*PAD + j], t[k]);
            }
#pragma unroll
            for (int j = 0; j < 16; j++) Ai[j] = t[j];
        }
        __syncthreads();
        if (jb < 7) {
            float tacc[8][8];
#pragma unroll
            for (int a = jb+1; a < 8; a++)
#pragma unroll
                for (int b = jb+1; b <= a; b++) tacc[a][b] = 0.0f;
            float pa[8], pb[8];
#pragma unroll
            for (int k = 0; k < 16; k++) {
#pragma unroll
                for (int a = jb+1; a < 8; a++) pa[a] = A[(ty + 16*a)*PAD + jb*16 + k];
#pragma unroll
                for (int b = jb+1; b < 8; b++) pb[b] = A[(tx + 16*b)*PAD + jb*16 + k];
#pragma unroll
                for (int a = jb+1; a < 8; a++)
#pragma unroll
                    for (int b = jb+1; b <= a; b++) tacc[a][b] += pa[a] * pb[b];
            }
#pragma unroll
            for (int a = jb+1; a < 8; a++)
#pragma unroll
                for (int b = jb+1; b <= a; b++)
                    A[(ty + 16*a)*PAD + tx + 16*b] -= tacc[a][b];
            __syncthreads();
        }
    }
}

__device__ __noinline__ void trsm_blocked(float* A, const float* dinv,
                                          float* scratch, int tid) {
    const int warp = tid >> 5;
    const int lane = tid & 31;
    const int c = lane & 15, rh = lane >> 4;
#pragma unroll
    for (int ib = 0; ib < 8; ib++) {
        if (warp == 7 && lane < 16) {
            const float* Ld = A + (ib*16)*PAD + ib*16;
            float dv[16], t[16];
#pragma unroll
            for (int r = 0; r < 16; r++) dv[r] = dinv[ib*16 + r];
#pragma unroll
            for (int r = 0; r < 16; r++) t[r] = (r == c) ? 1.0f : 0.0f;
#pragma unroll
            for (int r = 0; r < 16; r++) {
                float x = t[r] * dv[r];
                t[r] = x;
#pragma unroll
                for (int k = r + 1; k < 16; k++)
                    t[k] = fmaf(-x, Ld[k*PAD + r], t[k]);
            }
#pragma unroll
            for (int r = 0; r < 16; r++) scratch[8*272 + r*17 + c] = t[r];
        }
        float acc[8];
        if (warp < ib) {
#pragma unroll
            for (int q = 0; q < 8; q++) acc[q] = 0.0f;
            for (int kb = warp; kb < ib; kb++) {
#pragma unroll
                for (int k = 0; k < 16; k++) {
                    float xv = A[(kb*16 + k)*PAD + warp*16 + c];
#pragma unroll
                    for (int q = 0; q < 8; q++)
                        acc[q] -= A[(ib*16 + rh*8 + q)*PAD + kb*16 + k] * xv;
                }
            }
#pragma unroll
            for (int q = 0; q < 8; q++)
                scratch[warp*272 + (rh*8 + q)*17 + c] = acc[q];
        }
        __syncthreads();
        if (warp < ib) {
            const float* Dv = scratch + 8*272;
            const float* T  = scratch + warp*272;
#pragma unroll
            for (int q = 0; q < 8; q++) {
                const int r = rh*8 + q;
                float t = 0.0f;
#pragma unroll
                for (int k = 0; k < 16; k++) t += Dv[r*17 + k] * T[k*17 + c];
                A[(ib*16 + r)*PAD + warp*16 + c] = t;
            }
        }
        if (warp == 7 && lane < 16) {
            const float* Dv = scratch + 8*272;
#pragma unroll
            for (int r = 0; r < 16; r++)
                A[(ib*16 + r)*PAD + ib*16 + c] = Dv[r*17 + c];
        }
        __syncthreads();
    }
}

__global__ __launch_bounds__(256, 2)
void k1_factor(const float* __restrict__ U,
               const float* __restrict__ pmu,
               const float* __restrict__ plogprec,
               const float* __restrict__ eps) {
    extern __shared__ unsigned char smraw[];
    char* sm = (char*)smraw;
    const uint32_t smb = s2u(sm);

    float* A    = (float*)(sm + OFF_A);
    float* sqlp = (float*)(sm + OFF_SQLP);
    float* lpm  = (float*)(sm + OFF_LPM);
    float* utlv = (float*)(sm + OFF_UTLV);
    float* dinv = (float*)(sm + OFF_DINV);
    float* qmu  = (float*)(sm + OFF_QMU);
    float* epsv = (float*)(sm + OFF_EPSV);
    float* red  = (float*)(sm + OFF_RED);

    const int so = blockIdx.x;
    const int s = so >> 7;
    const int o = so & 127;
    const int tid = threadIdx.x;
    const int wid = tid >> 5;
    const int lane = tid & 31;

    if (tid < 128) {
        float l = expf(plogprec[o*MM + tid]);
        sqlp[tid] = sqrtf(l);
        lpm[tid]  = l * pmu[o*MM + tid];
        epsv[tid] = eps[(s*OO + o)*DD + tid];
    }
    __syncthreads();

    // ---- utlv[d] = sum_m lp*mu[m] * relu(U[m][d]) ----
    if (tid < 128) {
        const float* Ub = U + (size_t)s*MM*DD + tid;
        float a0=0.f, a1=0.f, a2=0.f, a3=0.f;
        for (int m = 0; m < 128; m += 4) {
            a0 = fmaf(lpm[m+0], fmaxf(Ub[(m+0)*DD], 0.f), a0);
            a1 = fmaf(lpm[m+1], fmaxf(Ub[(m+1)*DD], 0.f), a1);
            a2 = fmaf(lpm[m+2], fmaxf(Ub[(m+2)*DD], 0.f), a2);
            a3 = fmaf(lpm[m+3], fmaxf(Ub[(m+3)*DD], 0.f), a3);
        }
        utlv[tid] = (a0+a1) + (a2+a3);
    }

    // ---- per-warp lower-triangle tile list: 72 tiles (rb, jb<=2rb+1), 9/warp ----
    int rbv[9], jbv[9];
    {
        int t = 0, idx = 0;
        for (int rb = 0; rb < 8; rb++)
            for (int jb = 0; jb <= 2*rb + 1; jb++) {
                if ((idx & 7) == wid) { rbv[t] = rb; jbv[t] = jb; t++; }
                idx++;
            }
    }
    const int aRow = lane & 15;          // A-frag row within tile
    const int aColH = (lane >> 4) * 8;   // A-frag col half
    const int bRow = lane & 7;           // B-frag row (n) within tile
    const int bCol = (lane >> 3) * 8;    // B-frag col (k) quarter
    const uint32_t sb[3] = {smb + OFF_SB0, smb + OFF_SB1, smb + OFF_SB2};
    const int prA[6] = {0, 0, 1, 0, 2, 1};
    const int prB[6] = {0, 1, 0, 2, 0, 1};

    float cc[9][4];
#pragma unroll
    for (int t = 0; t < 9; t++)
#pragma unroll
        for (int q = 0; q < 4; q++) cc[t][q] = 0.f;

    // ================= Gram = P~^T P~ via HMMA, bf16x3 =================
#pragma unroll
    for (int c = 0; c < 4; c++) {
        // stage P~^T chunk: rows d 0..127, cols mloc 0..31 (m = 32c+mloc)
        for (int it = 0; it < 16; it++) {
            int idx = tid + it*256;
            int mloc = idx >> 7, d = idx & 127;
            float u = U[((size_t)s*MM + 32*c + mloc)*DD + d];
            float v = sqlp[32*c + mloc] * fmaxf(u, 0.f);
            __nv_bfloat16 h = __float2bfloat16(v);
            float r1 = v - __bfloat162float(h);
            __nv_bfloat16 md = __float2bfloat16(r1);
            __nv_bfloat16 lo = __float2bfloat16(r1 - __bfloat162float(md));
            int off = d*SB_STRIDE_B + mloc*2;
            *(__nv_bfloat16*)(sm + OFF_SB0 + off) = h;
            *(__nv_bfloat16*)(sm + OFF_SB1 + off) = md;
            *(__nv_bfloat16*)(sm + OFF_SB2 + off) = lo;
        }
        __syncthreads();
        for (int p = 0; p < 6; p++) {
            uint32_t Ab = sb[prA[p]];
            uint32_t Bb = sb[prB[p]];
#pragma unroll
            for (int t = 0; t < 9; t++) {
                uint32_t aAddr0 = Ab + (uint32_t)(rbv[t]*16 + aRow)*SB_STRIDE_B + (0 + aColH)*2;
                uint32_t aAddr1 = aAddr0 + 32;   // +16 cols * 2B
                uint32_t bAddr  = Bb + (uint32_t)(jbv[t]*8 + bRow)*SB_STRIDE_B + bCol*2;
                uint32_t a0,a1,a2,a3, e0,e1,e2,e3, b0,b1,b2,b3;
                ldsm_x4(aAddr0, a0,a1,a2,a3);
                ldsm_x4(aAddr1, e0,e1,e2,e3);
                ldsm_x4(bAddr,  b0,b1,b2,b3);
                mma16816(cc[t][0],cc[t][1],cc[t][2],cc[t][3], a0,a1,a2,a3, b0,b1);
                mma16816(cc[t][0],cc[t][1],cc[t][2],cc[t][3], e0,e1,e2,e3, b2,b3);
            }
        }
        __syncthreads();
    }
    // store Gram + I (lower tiles; diag-tile upper entries are valid Gram values)
    {
        const int g = lane >> 2, tc = (lane & 3) * 2;
#pragma unroll
        for (int t = 0; t < 9; t++) {
            int i0 = rbv[t]*16 + g, j0 = jbv[t]*8 + tc;
            A[i0*PAD + j0]       = cc[t][0] + (i0 == j0     ? 1.f : 0.f);
            A[i0*PAD + j0 + 1]   = cc[t][1] + (i0 == j0 + 1 ? 1.f : 0.f);
            A[(i0+8)*PAD + j0]   = cc[t][2] + (i0+8 == j0   ? 1.f : 0.f);
            A[(i0+8)*PAD + j0+1] = cc[t][3] + (i0+8 == j0+1 ? 1.f : 0.f);
        }
    }
    __syncthreads();

    // ---- L = chol(A); X = L^{-1} ----
    chol_blocked(A, dinv, tid);
    trsm_blocked(A, dinv, (float*)(sm + OFF_SCRATCH), tid);

    // ================= q_cov = X^T X via HMMA, bf16x3 =================
#pragma unroll
    for (int t = 0; t < 9; t++)
#pragma unroll
        for (int q = 0; q < 4; q++) cc[t][q] = 0.f;

#pragma unroll
    for (int c = 0; c < 4; c++) {
        // stage X^T chunk: rows i 0..127, cols kloc 0..31 (k = 32c+kloc)
        for (int it = 0; it < 16; it++) {
            int idx = tid + it*256;
            int kloc = idx >> 7, i = idx & 127;
            int k = 32*c + kloc;
            float x = (i <= k) ? A[k*PAD + i] : 0.f;
            __nv_bfloat16 h = __float2bfloat16(x);
            float r1 = x - __bfloat162float(h);
            __nv_bfloat16 md = __float2bfloat16(r1);
            __nv_bfloat16 lo = __float2bfloat16(r1 - __bfloat162float(md));
            int off = i*SB_STRIDE_B + kloc*2;
            *(__nv_bfloat16*)(sm + OFF_SB0 + off) = h;
            *(__nv_bfloat16*)(sm + OFF_SB1 + off) = md;
            *(__nv_bfloat16*)(sm + OFF_SB2 + off) = lo;
        }
        __syncthreads();
        const int rbmax = 2*c + 1;   // X rows i >= 32(c+1) are all-zero this chunk
        for (int p = 0; p < 6; p++) {
            uint32_t Ab = sb[prA[p]];
            uint32_t Bb = sb[prB[p]];
#pragma unroll
            for (int t = 0; t < 9; t++) {
                if (rbv[t] > rbmax) continue;
                uint32_t aAddr0 = Ab + (uint32_t)(rbv[t]*16 + aRow)*SB_STRIDE_B + (0 + aColH)*2;
                uint32_t aAddr1 = aAddr0 + 32;
                uint32_t bAddr  = Bb + (uint32_t)(jbv[t]*8 + bRow)*SB_STRIDE_B + bCol*2;
                uint32_t a0,a1,a2,a3, e0,e1,e2,e3, b0,b1,b2,b3;
                ldsm_x4(aAddr0, a0,a1,a2,a3);
                ldsm_x4(aAddr1, e0,e1,e2,e3);
                ldsm_x4(bAddr,  b0,b1,b2,b3);
                mma16816(cc[t][0],cc[t][1],cc[t][2],cc[t][3], a0,a1,a2,a3, b0,b1);
                mma16816(cc[t][0],cc[t][1],cc[t][2],cc[t][3], e0,e1,e2,e3, b2,b3);
            }
        }
        __syncthreads();
    }
    // store q_cov (direct + mirror for strictly-off-diagonal tiles)
    {
        const int g = lane >> 2, tc = (lane & 3) * 2;
#pragma unroll
        for (int t = 0; t < 9; t++) {
            int i0 = rbv[t]*16 + g, j0 = jbv[t]*8 + tc;
            A[i0*PAD + j0]       = cc[t][0];
            A[i0*PAD + j0 + 1]   = cc[t][1];
            A[(i0+8)*PAD + j0]   = cc[t][2];
            A[(i0+8)*PAD + j0+1] = cc[t][3];
            if ((jbv[t] >> 1) != rbv[t]) {   // not a diagonal-block tile
                A[j0*PAD + i0]       = cc[t][0];
                A[(j0+1)*PAD + i0]   = cc[t][1];
                A[j0*PAD + i0 + 8]   = cc[t][2];
                A[(j0+1)*PAD + i0+8] = cc[t][3];
            }
        }
    }
    __syncthreads();

    // ---- q_mu = q_cov @ utlv ----
    if (tid < 128) {
        float a = 0.0f;
#pragma unroll 8
        for (int e = 0; e < DD; e++) a += A[tid*PAD + e] * utlv[e];
        qmu[tid] = a;
    }
    __syncthreads();

    if (tid < 128) red[tid] = A[tid*PAD + tid] + qmu[tid]*qmu[tid];
    __syncthreads();
    float trmu = 0.0f;
    if (tid < 32) {
        float p = red[tid] + red[tid+32] + red[tid+64] + red[tid+96];
#pragma unroll
        for (int off = 16; off > 0; off >>= 1)
            p += __shfl_xor_sync(0xFFFFFFFFu, p, off);
        trmu = p;
    }
    __syncthreads();

    // ---- Lcov = chol(q_cov) ----
    chol_blocked(A, dinv, tid);

    if (tid < 128) red[tid] = logf(A[tid*PAD + tid]);
    __syncthreads();

    // ---- w = q_mu + Lcov @ eps ; KL ----
    if (tid < 128) {
        float a = qmu[tid];
        for (int e = 0; e <= tid; e++)
            a += A[tid*PAD + e] * epsv[e];
        g_w[(s*OO + o)*DD + tid] = a;
    }
    if (tid < 32) {
        float p = red[tid] + red[tid+32] + red[tid+64] + red[tid+96];
#pragma unroll
        for (int off = 16; off > 0; off >>= 1)
            p += __shfl_xor_sync(0xFFFFFFFFu, p, off);
        if (tid == 0)
            g_klso[so] = 0.5f * (trmu - (float)DD) - p;
    }
}

// ---- k2: F_out / U_out GEMMs, float4-over-k ----
#define KP 36
__global__ __launch_bounds__(256, 2)
void k2_gemm(const float* __restrict__ F, const float* __restrict__ U,
             float* __restrict__ outF, float* __restrict__ outU) {
    __shared__ float At[128*KP];
    __shared__ float Bt[128*KP];
    const int b = blockIdx.x;
    const int tid = threadIdx.x;
    const int ty = tid >> 4, tx = tid & 15;

    int s;
    const float* Ag;
    float* Cg;
    if (b < SS * (NN/128)) {
        s = b >> 5;
        int nt = b & 31;
        Ag = F + (size_t)(s*NN + nt*128) * DD;
        Cg = outF + (size_t)(s*NN + nt*128) * OO;
    } else {
        s = b - SS * (NN/128);
        Ag = U + (size_t)(s*MM) * DD;
        Cg = outU + (size_t)(s*MM) * OO;
    }
    const float* W = g_w + (size_t)s * OO * DD;

    float acc[8][8];
#pragma unroll
    for (int a = 0; a < 8; a++)
#pragma unroll
        for (int c = 0; c < 8; c++) acc[a][c] = 0.0f;

    for (int kb = 0; kb < DD; kb += 32) {
        __syncthreads();
        for (int idx = tid; idx < 128*8; idx += 256) {
            int r = idx >> 3, c4 = idx & 7;
            float4 v = *(const float4*)&Ag[r*DD + kb + 4*c4];
            v.x = fmaxf(v.x, 0.f); v.y = fmaxf(v.y, 0.f);
            v.z = fmaxf(v.z, 0.f); v.w = fmaxf(v.w, 0.f);
            *(float4*)&At[r*KP + 4*c4] = v;
            *(float4*)&Bt[r*KP + 4*c4] = *(const float4*)&W[r*DD + kb + 4*c4];
        }
        __syncthreads();
#pragma unroll
        for (int k4 = 0; k4 < 8; k4++) {
            float4 bv[8];
#pragma unroll
            for (int c = 0; c < 8; c++)
                bv[c] = *(const float4*)&Bt[(tx + 16*c)*KP + 4*k4];
#pragma unroll
            for (int a = 0; a < 8; a++) {
                float4 av = *(const float4*)&At[(ty + 16*a)*KP + 4*k4];
#pragma unroll
                for (int c = 0; c < 8; c++) {
                    acc[a][c] += av.x * bv[c].x;
                    acc[a][c] += av.y * bv[c].y;
                    acc[a][c] += av.z * bv[c].z;
                    acc[a][c] += av.w * bv[c].w;
                }
            }
        }
    }
#pragma unroll
    for (int a = 0; a < 8; a++)
#pragma unroll
        for (int c = 0; c < 8; c++)
            Cg[(ty + 16*a)*OO + tx + 16*c] = acc[a][c];
}

__global__ void k3_kl(float* __restrict__ kl) {
    int s = threadIdx.x;
    if (s < SS) {
        float a = 0.0f;
        for (int o = 0; o < OO; o++) a += g_klso[s*OO + o];
        kl[s] = a;
    }
}

extern "C" void kernel_launch(void* const* d_in, const int* in_sizes, int n_in,
                              void* d_out, int out_size) {
    const float* F        = (const float*)d_in[0];
    const float* U        = (const float*)d_in[1];
    const float* pmu      = (const float*)d_in[2];
    const float* plogprec = (const float*)d_in[3];
    const float* eps      = (const float*)d_in[4];

    float* out  = (float*)d_out;
    float* outF = out;
    float* outU = outF + (size_t)SS*NN*OO;
    float* outK = outU + (size_t)SS*MM*OO;

    cudaFuncSetAttribute(k1_factor, cudaFuncAttributeMaxDynamicSharedMemorySize,
                         SMEM_DYN);

    k1_factor<<<SS*OO, 256, SMEM_DYN>>>(U, pmu, plogprec, eps);
    k2_gemm<<<SS*(NN/128) + SS, 256>>>(F, U, outF, outU);
    k3_kl<<<1, 32>>>(outK);
}

// round 8
// speedup vs baseline: 1.0840x; 1.0840x over previous
#include <cuda_runtime.h>
#include <math.h>
#include <stdint.h>

#define SS 16
#define NN 4096
#define MM 128
#define DD 128
#define OO 128

__device__ float g_w[SS*OO*DD];
__device__ float g_klso[SS*OO];

// ---- smem layout (byte offsets) ----
#define OFF_RB     0        // int rb[128]
#define OFF_A      512      // packed lower triangle: 8256 floats = 33024 B
#define OFF_DD2    33536    // dense diag X-blocks: 8 x 272 floats = 8704 B
#define OFF_P      42240    // staging 32x132 floats = 16896 B ; trsm scratch aliases
#define OFF_LP     59136
#define OFF_LPM    59648
#define OFF_UTLV   60160
#define OFF_DINV   60672
#define OFF_QMU    61184
#define OFF_EPSV   61696
#define OFF_RED    62208
#define SMEM_DYN   62720

#define P_STRIDE 132

// 16x16 packed Cholesky of diag block jb by lanes 0..15 of warp 0.
__device__ __forceinline__ void chol16_packed(float* A, const int* rb, int jb, float* dinv) {
    const int lane = threadIdx.x & 31;
    if (lane < 16) {
        const int rbl = rb[jb*16 + lane] + jb*16;
        float row[16], rawv[16];
#pragma unroll
        for (int k = 0; k < 16; k++) row[k] = A[rbl + k];  // k>lane: garbage, unused
#pragma unroll
        for (int j = 0; j < 16; j++) {
            float raw = __shfl_sync(0xFFFFu, row[j], j);
            rawv[j] = raw;
            float inv = __fdividef(1.0f, raw);
            float tj = row[j] * inv;
#pragma unroll
            for (int k = j + 1; k < 16; k++) {
                float rkj = __shfl_sync(0xFFFFu, row[j], k);
                row[k] = fmaf(-tj, rkj, row[k]);
            }
        }
        float rs[16];
#pragma unroll
        for (int j = 0; j < 16; j++) rs[j] = rsqrtf(rawv[j]);
#pragma unroll
        for (int k = 0; k < 16; k++) {
            float v = (k < lane) ? row[k] * rs[k] : rawv[k] * rs[k];
            if (k <= lane) A[rbl + k] = v;     // packed: never write past own row
        }
        dinv[jb*16 + lane] = rs[lane];
    }
    __syncwarp();
}

// Blocked packed Cholesky (lower triangle in/out), dinv[j] = 1/L[j][j].
__device__ __noinline__ void chol_blocked_packed(float* A, const int* rb, float* dinv, int tid) {
    const int warp = tid >> 5;
    const int ty = tid >> 4, tx = tid & 15;
#pragma unroll
    for (int jb = 0; jb < 8; jb++) {
        if (warp == 0) chol16_packed(A, rb, jb, dinv);
        __syncthreads();
        const int nrows = 112 - jb*16;
        if (tid < nrows) {
            const int i = jb*16 + 16 + tid;
            const int rbi = rb[i] + jb*16;
            int rblk[16];
#pragma unroll
            for (int k = 0; k < 16; k++) rblk[k] = rb[jb*16 + k] + jb*16;
            float dv[16], t[16];
#pragma unroll
            for (int j = 0; j < 16; j++) dv[j] = dinv[jb*16 + j];
#pragma unroll
            for (int j = 0; j < 16; j++) t[j] = A[rbi + j];
#pragma unroll
            for (int j = 0; j < 16; j++) {
                float v = t[j] * dv[j];
                t[j] = v;
#pragma unroll
                for (int k = j + 1; k < 16; k++)
                    t[k] = fmaf(-v, A[rblk[k] + j], t[k]);
            }
#pragma unroll
            for (int j = 0; j < 16; j++) A[rbi + j] = t[j];
        }
        __syncthreads();
        if (jb < 7) {
            int rra[8], rrb[8];
#pragma unroll
            for (int a = jb+1; a < 8; a++) { rra[a] = rb[ty + 16*a]; rrb[a] = rb[tx + 16*a]; }
            float tacc[8][8];
#pragma unroll
            for (int a = jb+1; a < 8; a++)
#pragma unroll
                for (int b = jb+1; b <= a; b++) tacc[a][b] = 0.0f;
            float pa[8], pb[8];
#pragma unroll
            for (int k = 0; k < 16; k++) {
#pragma unroll
                for (int a = jb+1; a < 8; a++) pa[a] = A[rra[a] + jb*16 + k];
#pragma unroll
                for (int b = jb+1; b < 8; b++) pb[b] = A[rrb[b] + jb*16 + k];
#pragma unroll
                for (int a = jb+1; a < 8; a++)
#pragma unroll
                    for (int b = jb+1; b <= a; b++) tacc[a][b] += pa[a] * pb[b];
            }
#pragma unroll
            for (int a = jb+1; a < 8; a++)
#pragma unroll
                for (int b = jb+1; b <= a; b++) {
                    if (a > b || tx <= ty)
                        A[rra[a] + tx + 16*b] -= tacc[a][b];
                }
            __syncthreads();
        }
    }
}

// Blocked X = L^{-1} in place (packed). Diag inverse blocks also copied
// (zero-padded) into Ddense[ib*272 + r*17 + c].
__device__ __noinline__ void trsm_packed(float* A, const int* rb, const float* dinv,
                                         float* Ddense, float* scratch, int tid) {
    const int warp = tid >> 5;
    const int lane = tid & 31;
    const int c = lane & 15, rh = lane >> 4;
#pragma unroll
    for (int ib = 0; ib < 8; ib++) {
        if (warp == 7 && lane < 16) {
            int rbr[16];
#pragma unroll
            for (int r = 0; r < 16; r++) rbr[r] = rb[ib*16 + r] + ib*16;
            float dv[16], t[16];
#pragma unroll
            for (int r = 0; r < 16; r++) dv[r] = dinv[ib*16 + r];
#pragma unroll
            for (int r = 0; r < 16; r++) t[r] = (r == c) ? 1.0f : 0.0f;
#pragma unroll
            for (int r = 0; r < 16; r++) {
                float x = t[r] * dv[r];
                t[r] = x;
#pragma unroll
                for (int k = r + 1; k < 16; k++)
                    t[k] = fmaf(-x, A[rbr[k] + r], t[k]);
            }
#pragma unroll
            for (int r = 0; r < 16; r++) scratch[8*272 + r*17 + c] = t[r];
        }
        float acc[8];
        if (warp < ib) {
            int rbq[8];
#pragma unroll
            for (int q = 0; q < 8; q++) rbq[q] = rb[ib*16 + rh*8 + q];
#pragma unroll
            for (int q = 0; q < 8; q++) acc[q] = 0.0f;
            // kb == warp: X diag block from Ddense (zero-padded)
            {
#pragma unroll
                for (int k = 0; k < 16; k++) {
                    float xv = Ddense[warp*272 + k*17 + c];
#pragma unroll
                    for (int q = 0; q < 8; q++)
                        acc[q] -= A[rbq[q] + warp*16 + k] * xv;
                }
            }
            for (int kb = warp + 1; kb < ib; kb++) {
#pragma unroll
                for (int k = 0; k < 16; k++) {
                    float xv = A[rb[kb*16 + k] + warp*16 + c];
#pragma unroll
                    for (int q = 0; q < 8; q++)
                        acc[q] -= A[rbq[q] + kb*16 + k] * xv;
                }
            }
#pragma unroll
            for (int q = 0; q < 8; q++)
                scratch[warp*272 + (rh*8 + q)*17 + c] = acc[q];
        }
        __syncthreads();
        if (warp < ib) {
            const float* Dv = scratch + 8*272;
            const float* T  = scratch + warp*272;
#pragma unroll
            for (int q = 0; q < 8; q++) {
                const int r = rh*8 + q;
                float t = 0.0f;
#pragma unroll
                for (int k = 0; k < 16; k++) t += Dv[r*17 + k] * T[k*17 + c];
                A[rb[ib*16 + r] + warp*16 + c] = t;
            }
        }
        if (warp == 7 && lane < 16) {
            const float* Dv = scratch + 8*272;
#pragma unroll
            for (int r = 0; r < 16; r++) {
                float v = Dv[r*17 + c];
                Ddense[ib*272 + r*17 + c] = v;
                if (r >= c) A[rb[ib*16 + r] + ib*16 + c] = v;
            }
        }
        __syncthreads();
    }
}

__global__ __launch_bounds__(256, 3)
void k1_factor(const float* __restrict__ U,
               const float* __restrict__ pmu,
               const float* __restrict__ plogprec,
               const float* __restrict__ eps) {
    extern __shared__ unsigned char smraw[];
    char* sm = (char*)smraw;

    int*   rb    = (int*)(sm + OFF_RB);
    float* A     = (float*)(sm + OFF_A);
    float* Dd    = (float*)(sm + OFF_DD2);
    float* P     = (float*)(sm + OFF_P);
    float* lp    = (float*)(sm + OFF_LP);
    float* lpm   = (float*)(sm + OFF_LPM);
    float* utlv  = (float*)(sm + OFF_UTLV);
    float* dinv  = (float*)(sm + OFF_DINV);
    float* qmu   = (float*)(sm + OFF_QMU);
    float* epsv  = (float*)(sm + OFF_EPSV);
    float* red   = (float*)(sm + OFF_RED);

    const int so = blockIdx.x;
    const int s = so >> 7;
    const int o = so & 127;
    const int tid = threadIdx.x;
    const int ty = tid >> 4, tx = tid & 15;

    if (tid < 128) {
        rb[tid] = tid*(tid+1)/2;
        float l = expf(plogprec[o*MM + tid]);
        lp[tid]   = l;
        lpm[tid]  = l * pmu[o*MM + tid];
        epsv[tid] = eps[(s*OO + o)*DD + tid];
        utlv[tid] = 0.0f;
    }

    // ---- Gram: A = phiU^T diag(lp) phiU + I (packed lower), single-buffer P ----
    float acc[8][8];
#pragma unroll
    for (int a = 0; a < 8; a++)
#pragma unroll
        for (int b = 0; b <= a; b++) acc[a][b] = 0.0f;

#pragma unroll
    for (int c = 0; c < 4; c++) {
        __syncthreads();
        {
            const float4* Ug = (const float4*)(U + ((size_t)s*MM + c*32)*DD);
            for (int idx = tid; idx < 32*32; idx += 256) {
                int mm = idx >> 5, dq = idx & 31;
                float4 u = Ug[mm*32 + dq];
                u.x = fmaxf(u.x, 0.f); u.y = fmaxf(u.y, 0.f);
                u.z = fmaxf(u.z, 0.f); u.w = fmaxf(u.w, 0.f);
                *(float4*)&P[mm*P_STRIDE + 4*dq] = u;
            }
        }
        __syncthreads();
        if (tid < 128) {
            float a = 0.0f;
#pragma unroll 8
            for (int mm = 0; mm < 32; mm++)
                a += lpm[c*32 + mm] * P[mm*P_STRIDE + tid];
            utlv[tid] += a;
        }
        for (int mm = 0; mm < 32; mm++) {
            float wgt = lp[c*32 + mm];
            float pi[8], pj[8];
#pragma unroll
            for (int a = 0; a < 8; a++) pi[a] = P[mm*P_STRIDE + ty + 16*a];
#pragma unroll
            for (int b = 0; b < 8; b++) pj[b] = wgt * P[mm*P_STRIDE + tx + 16*b];
#pragma unroll
            for (int a = 0; a < 8; a++)
#pragma unroll
                for (int b = 0; b <= a; b++)
                    acc[a][b] += pi[a] * pj[b];
        }
    }
    __syncthreads();
#pragma unroll
    for (int a = 0; a < 8; a++) {
        const int ra = rb[ty + 16*a];
#pragma unroll
        for (int b = 0; b < a; b++)
            A[ra + tx + 16*b] = acc[a][b];
        if (tx <= ty)
            A[ra + tx + 16*a] = acc[a][a] + (tx == ty ? 1.0f : 0.0f);
    }
    __syncthreads();

    // ---- L = chol(A); X = L^{-1} (packed) ----
    chol_blocked_packed(A, rb, dinv, tid);
    trsm_packed(A, rb, dinv, Dd, P /*scratch alias*/, tid);

    // ---- q_cov = X^T X (packed, block-triangular k skip; diag blocks via Dd) ----
#pragma unroll
    for (int a = 0; a < 8; a++)
#pragma unroll
        for (int b = 0; b <= a; b++) acc[a][b] = 0.0f;
#pragma unroll
    for (int kb = 0; kb < 8; kb++) {
        for (int kk = 0; kk < 16; kk++) {
            const int rbk = rb[kb*16 + kk];
            float xi[8], xj[8];
#pragma unroll
            for (int a = 0; a < kb; a++) {
                xi[a] = A[rbk + ty + 16*a];
                xj[a] = A[rbk + tx + 16*a];
            }
            xi[kb] = Dd[kb*272 + kk*17 + ty];
            xj[kb] = Dd[kb*272 + kk*17 + tx];
#pragma unroll
            for (int a = 0; a <= kb; a++)
#pragma unroll
                for (int b = 0; b <= a; b++)
                    acc[a][b] += xi[a] * xj[b];
        }
    }
    __syncthreads();
#pragma unroll
    for (int a = 0; a < 8; a++) {
        const int ra = rb[ty + 16*a];
#pragma unroll
        for (int b = 0; b < a; b++)
            A[ra + tx + 16*b] = acc[a][b];
        if (tx <= ty)
            A[ra + tx + 16*a] = acc[a][a];
    }
    __syncthreads();

    // ---- q_mu = q_cov @ utlv (symmetric two-loop read of packed lower) ----
    if (tid < 128) {
        const int rbt = rb[tid];
        float a = 0.0f;
        for (int e = 0; e <= tid; e++)   a += A[rbt + e] * utlv[e];
        for (int e = tid + 1; e < 128; e++) a += A[rb[e] + tid] * utlv[e];
        qmu[tid] = a;
    }
    __syncthreads();

    if (tid < 128) red[tid] = A[rb[tid] + tid] + qmu[tid]*qmu[tid];
    __syncthreads();
    float trmu = 0.0f;
    if (tid < 32) {
        float p = red[tid] + red[tid+32] + red[tid+64] + red[tid+96];
#pragma unroll
        for (int off = 16; off > 0; off >>= 1)
            p += __shfl_xor_sync(0xFFFFFFFFu, p, off);
        trmu = p;
    }
    __syncthreads();

    // ---- Lcov = chol(q_cov) (packed) ----
    chol_blocked_packed(A, rb, dinv, tid);

    if (tid < 128) red[tid] = logf(A[rb[tid] + tid]);
    __syncthreads();

    // ---- w = q_mu + Lcov @ eps ; KL ----
    if (tid < 128) {
        const int rbt = rb[tid];
        float a = qmu[tid];
        for (int e = 0; e <= tid; e++)
            a += A[rbt + e] * epsv[e];
        g_w[(s*OO + o)*DD + tid] = a;
    }
    if (tid < 32) {
        float p = red[tid] + red[tid+32] + red[tid+64] + red[tid+96];
#pragma unroll
        for (int off = 16; off > 0; off >>= 1)
            p += __shfl_xor_sync(0xFFFFFFFFu, p, off);
        if (tid == 0)
            g_klso[so] = 0.5f * (trmu - (float)DD) - p;
    }
}

// ---- k2: F_out / U_out GEMMs, float4-over-k ----
#define KP 36
__global__ __launch_bounds__(256, 2)
void k2_gemm(const float* __restrict__ F, const float* __restrict__ U,
             float* __restrict__ outF, float* __restrict__ outU) {
    __shared__ float At[128*KP];
    __shared__ float Bt[128*KP];
    const int b = blockIdx.x;
    const int tid = threadIdx.x;
    const int ty = tid >> 4, tx = tid & 15;

    int s;
    const float* Ag;
    float* Cg;
    if (b < SS * (NN/128)) {
        s = b >> 5;
        int nt = b & 31;
        Ag = F + (size_t)(s*NN + nt*128) * DD;
        Cg = outF + (size_t)(s*NN + nt*128) * OO;
    } else {
        s = b - SS * (NN/128);
        Ag = U + (size_t)(s*MM) * DD;
        Cg = outU + (size_t)(s*MM) * OO;
    }
    const float* W = g_w + (size_t)s * OO * DD;

    float acc[8][8];
#pragma unroll
    for (int a = 0; a < 8; a++)
#pragma unroll
        for (int c = 0; c < 8; c++) acc[a][c] = 0.0f;

    for (int kb = 0; kb < DD; kb += 32) {
        __syncthreads();
        for (int idx = tid; idx < 128*8; idx += 256) {
            int r = idx >> 3, c4 = idx & 7;
            float4 v = *(const float4*)&Ag[r*DD + kb + 4*c4];
            v.x = fmaxf(v.x, 0.f); v.y = fmaxf(v.y, 0.f);
            v.z = fmaxf(v.z, 0.f); v.w = fmaxf(v.w, 0.f);
            *(float4*)&At[r*KP + 4*c4] = v;
            *(float4*)&Bt[r*KP + 4*c4] = *(const float4*)&W[r*DD + kb + 4*c4];
        }
        __syncthreads();
#pragma unroll
        for (int k4 = 0; k4 < 8; k4++) {
            float4 bv[8];
#pragma unroll
            for (int c = 0; c < 8; c++)
                bv[c] = *(const float4*)&Bt[(tx + 16*c)*KP + 4*k4];
#pragma unroll
            for (int a = 0; a < 8; a++) {
                float4 av = *(const float4*)&At[(ty + 16*a)*KP + 4*k4];
#pragma unroll
                for (int c = 0; c < 8; c++) {
                    acc[a][c] += av.x * bv[c].x;
                    acc[a][c] += av.y * bv[c].y;
                    acc[a][c] += av.z * bv[c].z;
                    acc[a][c] += av.w * bv[c].w;
                }
            }
        }
    }
#pragma unroll
    for (int a = 0; a < 8; a++)
#pragma unroll
        for (int c = 0; c < 8; c++)
            Cg[(ty + 16*a)*OO + tx + 16*c] = acc[a][c];
}

__global__ void k3_kl(float* __restrict__ kl) {
    int s = threadIdx.x;
    if (s < SS) {
        float a = 0.0f;
        for (int o = 0; o < OO; o++) a += g_klso[s*OO + o];
        kl[s] = a;
    }
}

extern "C" void kernel_launch(void* const* d_in, const int* in_sizes, int n_in,
                              void* d_out, int out_size) {
    const float* F        = (const float*)d_in[0];
    const float* U        = (const float*)d_in[1];
    const float* pmu      = (const float*)d_in[2];
    const float* plogprec = (const float*)d_in[3];
    const float* eps      = (const float*)d_in[4];

    float* out  = (float*)d_out;
    float* outF = out;
    float* outU = outF + (size_t)SS*NN*OO;
    float* outK = outU + (size_t)SS*MM*OO;

    cudaFuncSetAttribute(k1_factor, cudaFuncAttributeMaxDynamicSharedMemorySize,
                         SMEM_DYN);

    k1_factor<<<SS*OO, 256, SMEM_DYN>>>(U, pmu, plogprec, eps);
    k2_gemm<<<SS*(NN/128) + SS, 256>>>(F, U, outF, outU);
    k3_kl<<<1, 32>>>(outK);
}

// round 9
// speedup vs baseline: 1.1617x; 1.0716x over previous
#include <cuda_runtime.h>
#include <cuda_bf16.h>
#include <math.h>
#include <stdint.h>

#define SS 16
#define NN 4096
#define MM 128
#define DD 128
#define OO 128
#define PAD 129

__device__ float g_w[SS*OO*DD];
__device__ float g_klso[SS*OO];

// ---- smem layout (byte offsets) ----
#define OFF_A      0        // float A[128*129] = 66048 B
#define OFF_SB0    66560    // bf16 [128 rows][40] (32 data + 8 pad) = 10240 B
#define OFF_SB1    76800    // swapped buffer, same shape
#define OFF_P      87040    // staging P[16][129] floats (8256 B); trsm scratch (9792 B) aliases
#define OFF_SQLP   96832
#define OFF_SMU    97344
#define OFF_UTLV   97856
#define OFF_DINV   98368
#define OFF_QMU    98880
#define OFF_EPSV   99392
#define OFF_RED    99904
#define SMEM_DYN   100480

#define SB_STRIDE_B 80      // bytes per SB row (16B multiple)
#define P_STRIDE    129

__device__ __forceinline__ uint32_t s2u(const void* p) {
    uint32_t a;
    asm("{ .reg .u64 t; cvta.to.shared.u64 t, %1; cvt.u32.u64 %0, t; }"
        : "=r"(a) : "l"(p));
    return a;
}

__device__ __forceinline__ void ldsm_x4(uint32_t addr, uint32_t& r0, uint32_t& r1,
                                        uint32_t& r2, uint32_t& r3) {
    asm volatile("ldmatrix.sync.aligned.m8n8.x4.shared.b16 {%0,%1,%2,%3}, [%4];"
                 : "=r"(r0), "=r"(r1), "=r"(r2), "=r"(r3) : "r"(addr));
}

__device__ __forceinline__ void mma16816(float& c0, float& c1, float& c2, float& c3,
                                         uint32_t a0, uint32_t a1, uint32_t a2, uint32_t a3,
                                         uint32_t b0, uint32_t b1) {
    asm volatile(
        "mma.sync.aligned.m16n8k16.row.col.f32.bf16.bf16.f32 "
        "{%0,%1,%2,%3}, {%4,%5,%6,%7}, {%8,%9}, {%0,%1,%2,%3};"
        : "+f"(c0), "+f"(c1), "+f"(c2), "+f"(c3)
        : "r"(a0), "r"(a1), "r"(a2), "r"(a3), "r"(b0), "r"(b1));
}

__device__ __forceinline__ uint32_t pack_bf2(__nv_bfloat16 lo, __nv_bfloat16 hi) {
    uint16_t a = __bfloat16_as_ushort(lo), b = __bfloat16_as_ushort(hi);
    return (uint32_t)a | ((uint32_t)b << 16);
}

// ---- 16x16 warp Cholesky (lanes 0..15 of calling warp) ----
__device__ __forceinline__ void chol16_warp(float* A, float* dinv) {
    const int lane = threadIdx.x & 31;
    if (lane < 16) {
        float row[16], rawv[16];
#pragma unroll
        for (int k = 0; k < 16; k++) row[k] = A[lane*PAD + k];
#pragma unroll
        for (int j = 0; j < 16; j++) {
            float raw = __shfl_sync(0xFFFFu, row[j], j);
            rawv[j] = raw;
            float inv = __fdividef(1.0f, raw);
            float tj = row[j] * inv;
#pragma unroll
            for (int k = j + 1; k < 16; k++) {
                float rkj = __shfl_sync(0xFFFFu, row[j], k);
                row[k] = fmaf(-tj, rkj, row[k]);
            }
        }
        float rs[16];
#pragma unroll
        for (int j = 0; j < 16; j++) rs[j] = rsqrtf(rawv[j]);
#pragma unroll
        for (int k = 0; k < 16; k++) {
            float v = (k < lane) ? row[k] * rs[k] : rawv[k] * rs[k];
            A[lane*PAD + k] = v;
        }
        dinv[lane] = rs[lane];
    }
    __syncwarp();
}

__device__ __noinline__ void chol_blocked(float* A, float* dinv, int tid) {
    const int warp = tid >> 5;
    const int ty = tid >> 4, tx = tid & 15;
#pragma unroll
    for (int jb = 0; jb < 8; jb++) {
        if (warp == 0) chol16_warp(A + (jb*16)*PAD + jb*16, dinv + jb*16);
        __syncthreads();
        const int nrows = 112 - jb*16;
        if (tid < nrows) {
            const int i = jb*16 + 16 + tid;
            const float* Ld = A + (jb*16)*PAD + jb*16;
            float* Ai = A + i*PAD + jb*16;
            float dv[16], t[16];
#pragma unroll
            for (int j = 0; j < 16; j++) dv[j] = dinv[jb*16 + j];
#pragma unroll
            for (int j = 0; j < 16; j++) t[j] = Ai[j];
#pragma unroll
            for (int j = 0; j < 16; j++) {
                float v = t[j] * dv[j];
                t[j] = v;
#pragma unroll
                for (int k = j + 1; k < 16; k++)
                    t[k] = fmaf(-v, Ld[k*PAD + j], t[k]);
            }
#pragma unroll
            for (int j = 0; j < 16; j++) Ai[j] = t[j];
        }
        __syncthreads();
        if (jb < 7) {
            float tacc[8][8];
#pragma unroll
            for (int a = jb+1; a < 8; a++)
#pragma unroll
                for (int b = jb+1; b <= a; b++) tacc[a][b] = 0.0f;
            float pa[8], pb[8];
#pragma unroll
            for (int k = 0; k < 16; k++) {
#pragma unroll
                for (int a = jb+1; a < 8; a++) pa[a] = A[(ty + 16*a)*PAD + jb*16 + k];
#pragma unroll
                for (int b = jb+1; b < 8; b++) pb[b] = A[(tx + 16*b)*PAD + jb*16 + k];
#pragma unroll
                for (int a = jb+1; a < 8; a++)
#pragma unroll
                    for (int b = jb+1; b <= a; b++) tacc[a][b] += pa[a] * pb[b];
            }
#pragma unroll
            for (int a = jb+1; a < 8; a++)
#pragma unroll
                for (int b = jb+1; b <= a; b++)
                    A[(ty + 16*a)*PAD + tx + 16*b] -= tacc[a][b];
            __syncthreads();
        }
    }
}

__device__ __noinline__ void trsm_blocked(float* A, const float* dinv,
                                          float* scratch, int tid) {
    const int warp = tid >> 5;
    const int lane = tid & 31;
    const int c = lane & 15, rh = lane >> 4;
#pragma unroll
    for (int ib = 0; ib < 8; ib++) {
        if (warp == 7 && lane < 16) {
            const float* Ld = A + (ib*16)*PAD + ib*16;
            float dv[16], t[16];
#pragma unroll
            for (int r = 0; r < 16; r++) dv[r] = dinv[ib*16 + r];
#pragma unroll
            for (int r = 0; r < 16; r++) t[r] = (r == c) ? 1.0f : 0.0f;
#pragma unroll
            for (int r = 0; r < 16; r++) {
                float x = t[r] * dv[r];
                t[r] = x;
#pragma unroll
                for (int k = r + 1; k < 16; k++)
                    t[k] = fmaf(-x, Ld[k*PAD + r], t[k]);
            }
#pragma unroll
            for (int r = 0; r < 16; r++) scratch[8*272 + r*17 + c] = t[r];
        }
        float acc[8];
        if (warp < ib) {
#pragma unroll
            for (int q = 0; q < 8; q++) acc[q] = 0.0f;
            for (int kb = warp; kb < ib; kb++) {
#pragma unroll
                for (int k = 0; k < 16; k++) {
                    float xv = A[(kb*16 + k)*PAD + warp*16 + c];
#pragma unroll
                    for (int q = 0; q < 8; q++)
                        acc[q] -= A[(ib*16 + rh*8 + q)*PAD + kb*16 + k] * xv;
                }
            }
#pragma unroll
            for (int q = 0; q < 8; q++)
                scratch[warp*272 + (rh*8 + q)*17 + c] = acc[q];
        }
        __syncthreads();
        if (warp < ib) {
            const float* Dv = scratch + 8*272;
            const float* T  = scratch + warp*272;
#pragma unroll
            for (int q = 0; q < 8; q++) {
                const int r = rh*8 + q;
                float t = 0.0f;
#pragma unroll
                for (int k = 0; k < 16; k++) t += Dv[r*17 + k] * T[k*17 + c];
                A[(ib*16 + r)*PAD + warp*16 + c] = t;
            }
        }
        if (warp == 7 && lane < 16) {
            const float* Dv = scratch + 8*272;
#pragma unroll
            for (int r = 0; r < 16; r++)
                A[(ib*16 + r)*PAD + ib*16 + c] = Dv[r*17 + c];
        }
        __syncthreads();
    }
}

__global__ __launch_bounds__(256, 2)
void k1_factor(const float* __restrict__ U,
               const float* __restrict__ pmu,
               const float* __restrict__ plogprec,
               const float* __restrict__ eps) {
    extern __shared__ unsigned char smraw[];
    char* sm = (char*)smraw;
    const uint32_t smb = s2u(sm);

    float* A    = (float*)(sm + OFF_A);
    float* P    = (float*)(sm + OFF_P);
    float* sqlp = (float*)(sm + OFF_SQLP);
    float* smu  = (float*)(sm + OFF_SMU);
    float* utlv = (float*)(sm + OFF_UTLV);
    float* dinv = (float*)(sm + OFF_DINV);
    float* qmu  = (float*)(sm + OFF_QMU);
    float* epsv = (float*)(sm + OFF_EPSV);
    float* red  = (float*)(sm + OFF_RED);

    const int so = blockIdx.x;
    const int s = so >> 7;
    const int o = so & 127;
    const int tid = threadIdx.x;
    const int wid = tid >> 5;
    const int lane = tid & 31;

    if (tid < 128) {
        float l = expf(plogprec[o*MM + tid]);
        float sq = sqrtf(l);
        sqlp[tid] = sq;
        smu[tid]  = sq * pmu[o*MM + tid];   // smu * (sqlp*relu) == lp*mu*relu
        epsv[tid] = eps[(s*OO + o)*DD + tid];
        utlv[tid] = 0.0f;
    }

    // ---- tile lists: 72 lower tiles (rb, jb <= 2rb+1), 9/warp ----
    int rbv[9], jbv[9];
    {
        int t = 0, idx = 0;
        for (int rb = 0; rb < 8; rb++)
            for (int jb = 0; jb <= 2*rb + 1; jb++) {
                if ((idx & 7) == wid) { rbv[t] = rb; jbv[t] = jb; t++; }
                idx++;
            }
    }
    const int aRow  = lane & 15;
    const int aColH = (lane >> 4) * 8;
    const int bRow  = lane & 7;
    const int bCol  = (lane >> 3) * 8;

    float cc[9][4];
#pragma unroll
    for (int t = 0; t < 9; t++)
#pragma unroll
        for (int q = 0; q < 4; q++) cc[t][q] = 0.f;

    // ============ Gram = P~^T P~  (2-pass interleaved bf16x2) ============
    for (int c = 0; c < 8; c++) {
        __syncthreads();   // protect SB (prev mma reads) and P before restage
        // stage P chunk: 16 m-rows x 128 d (coalesced global)
#pragma unroll
        for (int it = 0; it < 8; it++) {
            int idx = tid + it*256;
            int d = idx & 127, ml = idx >> 7;
            float u = U[((size_t)s*MM + c*16 + ml)*DD + d];
            P[ml*P_STRIDE + d] = sqlp[c*16 + ml] * fmaxf(u, 0.f);
        }
        __syncthreads();
        // utlv partial
        if (tid < 128) {
            float a = utlv[tid];
#pragma unroll
            for (int ml = 0; ml < 16; ml++)
                a = fmaf(smu[c*16 + ml], P[ml*P_STRIDE + tid], a);
            utlv[tid] = a;
        }
        // convert: SB0[d][2m]=(h,m), SB1[d][2m]=(m,h)
#pragma unroll
        for (int it = 0; it < 8; it++) {
            int idx = tid + it*256;
            int ml = idx & 15, d = idx >> 4;
            float v = P[ml*P_STRIDE + d];
            __nv_bfloat16 h = __float2bfloat16(v);
            __nv_bfloat16 m2 = __float2bfloat16(v - __bfloat162float(h));
            *(uint32_t*)(sm + OFF_SB0 + d*SB_STRIDE_B + ml*4) = pack_bf2(h, m2);
            *(uint32_t*)(sm + OFF_SB1 + d*SB_STRIDE_B + ml*4) = pack_bf2(m2, h);
        }
        __syncthreads();
        // mma: pass1 (SB0,SB0) + pass2 (SB0,SB1), A-frags reused
#pragma unroll
        for (int t = 0; t < 9; t++) {
            uint32_t aBase = smb + OFF_SB0 + (uint32_t)(rbv[t]*16 + aRow)*SB_STRIDE_B + aColH*2;
            uint32_t a0,a1,a2,a3, e0,e1,e2,e3;
            ldsm_x4(aBase,      a0,a1,a2,a3);
            ldsm_x4(aBase + 32, e0,e1,e2,e3);
            uint32_t bA0 = smb + OFF_SB0 + (uint32_t)(jbv[t]*8 + bRow)*SB_STRIDE_B + bCol*2;
            uint32_t b0,b1,b2,b3;
            ldsm_x4(bA0, b0,b1,b2,b3);
            mma16816(cc[t][0],cc[t][1],cc[t][2],cc[t][3], a0,a1,a2,a3, b0,b1);
            mma16816(cc[t][0],cc[t][1],cc[t][2],cc[t][3], e0,e1,e2,e3, b2,b3);
            uint32_t bA1 = smb + OFF_SB1 + (uint32_t)(jbv[t]*8 + bRow)*SB_STRIDE_B + bCol*2;
            uint32_t f0,f1,f2,f3;
            ldsm_x4(bA1, f0,f1,f2,f3);
            mma16816(cc[t][0],cc[t][1],cc[t][2],cc[t][3], a0,a1,a2,a3, f0,f1);
            mma16816(cc[t][0],cc[t][1],cc[t][2],cc[t][3], e0,e1,e2,e3, f2,f3);
        }
    }
    __syncthreads();
    // store Gram + I
    {
        const int g = lane >> 2, tc = (lane & 3) * 2;
#pragma unroll
        for (int t = 0; t < 9; t++) {
            int i0 = rbv[t]*16 + g, j0 = jbv[t]*8 + tc;
            A[i0*PAD + j0]       = cc[t][0] + (i0 == j0     ? 1.f : 0.f);
            A[i0*PAD + j0 + 1]   = cc[t][1] + (i0 == j0 + 1 ? 1.f : 0.f);
            A[(i0+8)*PAD + j0]   = cc[t][2] + (i0+8 == j0   ? 1.f : 0.f);
            A[(i0+8)*PAD + j0+1] = cc[t][3] + (i0+8 == j0+1 ? 1.f : 0.f);
        }
    }
    __syncthreads();

    // ---- L = chol(A); X = L^{-1} ----
    chol_blocked(A, dinv, tid);
    trsm_blocked(A, dinv, P /*scratch alias*/, tid);

    // ============ q_cov = X^T X  (same scheme, block-triangular skip) ============
#pragma unroll
    for (int t = 0; t < 9; t++)
#pragma unroll
        for (int q = 0; q < 4; q++) cc[t][q] = 0.f;

    for (int c = 0; c < 8; c++) {
        // stage X^T chunk: rows i 0..127, cols kloc 0..15 (k = 16c+kloc)
#pragma unroll
        for (int it = 0; it < 8; it++) {
            int idx = tid + it*256;
            int kl = idx & 15, i = idx >> 4;
            int k = c*16 + kl;
            float v = (i <= k) ? A[k*PAD + i] : 0.f;
            __nv_bfloat16 h = __float2bfloat16(v);
            __nv_bfloat16 m2 = __float2bfloat16(v - __bfloat162float(h));
            *(uint32_t*)(sm + OFF_SB0 + i*SB_STRIDE_B + kl*4) = pack_bf2(h, m2);
            *(uint32_t*)(sm + OFF_SB1 + i*SB_STRIDE_B + kl*4) = pack_bf2(m2, h);
        }
        __syncthreads();
#pragma unroll
        for (int t = 0; t < 9; t++) {
            if (rbv[t] > c) continue;   // zero contribution this chunk
            uint32_t aBase = smb + OFF_SB0 + (uint32_t)(rbv[t]*16 + aRow)*SB_STRIDE_B + aColH*2;
            uint32_t a0,a1,a2,a3, e0,e1,e2,e3;
            ldsm_x4(aBase,      a0,a1,a2,a3);
            ldsm_x4(aBase + 32, e0,e1,e2,e3);
            uint32_t bA0 = smb + OFF_SB0 + (uint32_t)(jbv[t]*8 + bRow)*SB_STRIDE_B + bCol*2;
            uint32_t b0,b1,b2,b3;
            ldsm_x4(bA0, b0,b1,b2,b3);
            mma16816(cc[t][0],cc[t][1],cc[t][2],cc[t][3], a0,a1,a2,a3, b0,b1);
            mma16816(cc[t][0],cc[t][1],cc[t][2],cc[t][3], e0,e1,e2,e3, b2,b3);
            uint32_t bA1 = smb + OFF_SB1 + (uint32_t)(jbv[t]*8 + bRow)*SB_STRIDE_B + bCol*2;
            uint32_t f0,f1,f2,f3;
            ldsm_x4(bA1, f0,f1,f2,f3);
            mma16816(cc[t][0],cc[t][1],cc[t][2],cc[t][3], a0,a1,a2,a3, f0,f1);
            mma16816(cc[t][0],cc[t][1],cc[t][2],cc[t][3], e0,e1,e2,e3, f2,f3);
        }
        __syncthreads();   // mma reads done before next restage
    }
    // store q_cov (direct + mirror for strictly-off-diagonal tiles)
    {
        const int g = lane >> 2, tc = (lane & 3) * 2;
#pragma unroll
        for (int t = 0; t < 9; t++) {
            int i0 = rbv[t]*16 + g, j0 = jbv[t]*8 + tc;
            A[i0*PAD + j0]       = cc[t][0];
            A[i0*PAD + j0 + 1]   = cc[t][1];
            A[(i0+8)*PAD + j0]   = cc[t][2];
            A[(i0+8)*PAD + j0+1] = cc[t][3];
            if ((jbv[t] >> 1) != rbv[t]) {
                A[j0*PAD + i0]       = cc[t][0];
                A[(j0+1)*PAD + i0]   = cc[t][1];
                A[j0*PAD + i0 + 8]   = cc[t][2];
                A[(j0+1)*PAD + i0+8] = cc[t][3];
            }
        }
    }
    __syncthreads();

    // ---- q_mu = q_cov @ utlv ----
    if (tid < 128) {
        float a = 0.0f;
#pragma unroll 8
        for (int e = 0; e < DD; e++) a += A[tid*PAD + e] * utlv[e];
        qmu[tid] = a;
    }
    __syncthreads();

    if (tid < 128) red[tid] = A[tid*PAD + tid] + qmu[tid]*qmu[tid];
    __syncthreads();
    float trmu = 0.0f;
    if (tid < 32) {
        float p = red[tid] + red[tid+32] + red[tid+64] + red[tid+96];
#pragma unroll
        for (int off = 16; off > 0; off >>= 1)
            p += __shfl_xor_sync(0xFFFFFFFFu, p, off);
        trmu = p;
    }
    __syncthreads();

    // ---- Lcov = chol(q_cov) ----
    chol_blocked(A, dinv, tid);

    if (tid < 128) red[tid] = logf(A[tid*PAD + tid]);
    __syncthreads();

    // ---- w = q_mu + Lcov @ eps ; KL ----
    if (tid < 128) {
        float a = qmu[tid];
        for (int e = 0; e <= tid; e++)
            a += A[tid*PAD + e] * epsv[e];
        g_w[(s*OO + o)*DD + tid] = a;
    }
    if (tid < 32) {
        float p = red[tid] + red[tid+32] + red[tid+64] + red[tid+96];
#pragma unroll
        for (int off = 16; off > 0; off >>= 1)
            p += __shfl_xor_sync(0xFFFFFFFFu, p, off);
        if (tid == 0)
            g_klso[so] = 0.5f * (trmu - (float)DD) - p;
    }
}

// ---- k2: F_out / U_out GEMMs, float4-over-k ----
#define KP 36
__global__ __launch_bounds__(256, 2)
void k2_gemm(const float* __restrict__ F, const float* __restrict__ U,
             float* __restrict__ outF, float* __restrict__ outU) {
    __shared__ float At[128*KP];
    __shared__ float Bt[128*KP];
    const int b = blockIdx.x;
    const int tid = threadIdx.x;
    const int ty = tid >> 4, tx = tid & 15;

    int s;
    const float* Ag;
    float* Cg;
    if (b < SS * (NN/128)) {
        s = b >> 5;
        int nt = b & 31;
        Ag = F + (size_t)(s*NN + nt*128) * DD;
        Cg = outF + (size_t)(s*NN + nt*128) * OO;
    } else {
        s = b - SS * (NN/128);
        Ag = U + (size_t)(s*MM) * DD;
        Cg = outU + (size_t)(s*MM) * OO;
    }
    const float* W = g_w + (size_t)s * OO * DD;

    float acc[8][8];
#pragma unroll
    for (int a = 0; a < 8; a++)
#pragma unroll
        for (int c = 0; c < 8; c++) acc[a][c] = 0.0f;

    for (int kb = 0; kb < DD; kb += 32) {
        __syncthreads();
        for (int idx = tid; idx < 128*8; idx += 256) {
            int r = idx >> 3, c4 = idx & 7;
            float4 v = *(const float4*)&Ag[r*DD + kb + 4*c4];
            v.x = fmaxf(v.x, 0.f); v.y = fmaxf(v.y, 0.f);
            v.z = fmaxf(v.z, 0.f); v.w = fmaxf(v.w, 0.f);
            *(float4*)&At[r*KP + 4*c4] = v;
            *(float4*)&Bt[r*KP + 4*c4] = *(const float4*)&W[r*DD + kb + 4*c4];
        }
        __syncthreads();
#pragma unroll
        for (int k4 = 0; k4 < 8; k4++) {
            float4 bv[8];
#pragma unroll
            for (int c = 0; c < 8; c++)
                bv[c] = *(const float4*)&Bt[(tx + 16*c)*KP + 4*k4];
#pragma unroll
            for (int a = 0; a < 8; a++) {
                float4 av = *(const float4*)&At[(ty + 16*a)*KP + 4*k4];
#pragma unroll
                for (int c = 0; c < 8; c++) {
                    acc[a][c] += av.x * bv[c].x;
                    acc[a][c] += av.y * bv[c].y;
                    acc[a][c] += av.z * bv[c].z;
                    acc[a][c] += av.w * bv[c].w;
                }
            }
        }
    }
#pragma unroll
    for (int a = 0; a < 8; a++)
#pragma unroll
        for (int c = 0; c < 8; c++)
            Cg[(ty + 16*a)*OO + tx + 16*c] = acc[a][c];
}

__global__ void k3_kl(float* __restrict__ kl) {
    int s = threadIdx.x;
    if (s < SS) {
        float a = 0.0f;
        for (int o = 0; o < OO; o++) a += g_klso[s*OO + o];
        kl[s] = a;
    }
}

extern "C" void kernel_launch(void* const* d_in, const int* in_sizes, int n_in,
                              void* d_out, int out_size) {
    const float* F        = (const float*)d_in[0];
    const float* U        = (const float*)d_in[1];
    const float* pmu      = (const float*)d_in[2];
    const float* plogprec = (const float*)d_in[3];
    const float* eps      = (const float*)d_in[4];

    float* out  = (float*)d_out;
    float* outF = out;
    float* outU = outF + (size_t)SS*NN*OO;
    float* outK = outU + (size_t)SS*MM*OO;

    cudaFuncSetAttribute(k1_factor, cudaFuncAttributeMaxDynamicSharedMemorySize,
                         SMEM_DYN);

    k1_factor<<<SS*OO, 256, SMEM_DYN>>>(U, pmu, plogprec, eps);
    k2_gemm<<<SS*(NN/128) + SS, 256>>>(F, U, outF, outU);
    k3_kl<<<1, 32>>>(outK);
}

// round 10
// speedup vs baseline: 1.2233x; 1.0531x over previous
#include <cuda_runtime.h>
#include <cuda_bf16.h>
#include <math.h>
#include <stdint.h>

#define SS 16
#define NN 4096
#define MM 128
#define DD 128
#define OO 128
#define PAD 129

__device__ float g_w[SS*OO*DD];
__device__ float g_klso[SS*OO];

// ---- smem layout (byte offsets) ----
#define OFF_A      0        // float A[128*129] = 66048 B
#define OFF_SB0    66560    // bf16 [128 rows][72] (64 data + 8 pad) = 18432 B
#define OFF_P      84992    // staging P[32][129] floats = 16512 B
#define OFF_SQLP   101888
#define OFF_SMU    102400
#define OFF_UTLV   102912
#define OFF_DINV   103424
#define OFF_QMU    103936
#define OFF_EPSV   104448
#define OFF_RED    104960
#define SMEM_DYN   105472
// trsm scratch (9792 B) aliases SB0 region (disjoint in time)
#define OFF_SCRATCH OFF_SB0

#define SB_STRIDE_B 144     // bytes per SB row (16B multiple): 64 doubled-k bf16 + pad
#define P_STRIDE    129

__device__ __forceinline__ uint32_t s2u(const void* p) {
    uint32_t a;
    asm("{ .reg .u64 t; cvta.to.shared.u64 t, %1; cvt.u32.u64 %0, t; }"
        : "=r"(a) : "l"(p));
    return a;
}

__device__ __forceinline__ void ldsm_x4(uint32_t addr, uint32_t& r0, uint32_t& r1,
                                        uint32_t& r2, uint32_t& r3) {
    asm volatile("ldmatrix.sync.aligned.m8n8.x4.shared.b16 {%0,%1,%2,%3}, [%4];"
                 : "=r"(r0), "=r"(r1), "=r"(r2), "=r"(r3) : "r"(addr));
}

__device__ __forceinline__ void mma16816(float& c0, float& c1, float& c2, float& c3,
                                         uint32_t a0, uint32_t a1, uint32_t a2, uint32_t a3,
                                         uint32_t b0, uint32_t b1) {
    asm volatile(
        "mma.sync.aligned.m16n8k16.row.col.f32.bf16.bf16.f32 "
        "{%0,%1,%2,%3}, {%4,%5,%6,%7}, {%8,%9}, {%0,%1,%2,%3};"
        : "+f"(c0), "+f"(c1), "+f"(c2), "+f"(c3)
        : "r"(a0), "r"(a1), "r"(a2), "r"(a3), "r"(b0), "r"(b1));
}

__device__ __forceinline__ uint32_t pack_bf2(__nv_bfloat16 lo, __nv_bfloat16 hi) {
    uint16_t a = __bfloat16_as_ushort(lo), b = __bfloat16_as_ushort(hi);
    return (uint32_t)a | ((uint32_t)b << 16);
}
__device__ __forceinline__ uint32_t swap16(uint32_t x) {
    return __byte_perm(x, x, 0x1032);
}

// ---- 16x16 warp Cholesky (lanes 0..15 of calling warp) ----
__device__ __forceinline__ void chol16_warp(float* A, float* dinv) {
    const int lane = threadIdx.x & 31;
    if (lane < 16) {
        float row[16], rawv[16];
#pragma unroll
        for (int k = 0; k < 16; k++) row[k] = A[lane*PAD + k];
#pragma unroll
        for (int j = 0; j < 16; j++) {
            float raw = __shfl_sync(0xFFFFu, row[j], j);
            rawv[j] = raw;
            float inv = __fdividef(1.0f, raw);
            float tj = row[j] * inv;
#pragma unroll
            for (int k = j + 1; k < 16; k++) {
                float rkj = __shfl_sync(0xFFFFu, row[j], k);
                row[k] = fmaf(-tj, rkj, row[k]);
            }
        }
        float rs[16];
#pragma unroll
        for (int j = 0; j < 16; j++) rs[j] = rsqrtf(rawv[j]);
#pragma unroll
        for (int k = 0; k < 16; k++) {
            float v = (k < lane) ? row[k] * rs[k] : rawv[k] * rs[k];
            A[lane*PAD + k] = v;
        }
        dinv[lane] = rs[lane];
    }
    __syncwarp();
}

__device__ __noinline__ void chol_blocked(float* A, float* dinv, int tid) {
    const int warp = tid >> 5;
    const int ty = tid >> 4, tx = tid & 15;
#pragma unroll
    for (int jb = 0; jb < 8; jb++) {
        if (warp == 0) chol16_warp(A + (jb*16)*PAD + jb*16, dinv + jb*16);
        __syncthreads();
        const int nrows = 112 - jb*16;
        if (tid < nrows) {
            const int i = jb*16 + 16 + tid;
            const float* Ld = A + (jb*16)*PAD + jb*16;
            float* Ai = A + i*PAD + jb*16;
            float dv[16], t[16];
#pragma unroll
            for (int j = 0; j < 16; j++) dv[j] = dinv[jb*16 + j];
#pragma unroll
            for (int j = 0; j < 16; j++) t[j] = Ai[j];
#pragma unroll
            for (int j = 0; j < 16; j++) {
                float v = t[j] * dv[j];
                t[j] = v;
#pragma unroll
                for (int k = j + 1; k < 16; k++)
                    t[k] = fmaf(-v, Ld[k*PAD + j], t[k]);
            }
#pragma unroll
            for (int j = 0; j < 16; j++) Ai[j] = t[j];
        }
        __syncthreads();
        if (jb < 7) {
            float tacc[8][8];
#pragma unroll
            for (int a = jb+1; a < 8; a++)
#pragma unroll
                for (int b = jb+1; b <= a; b++) tacc[a][b] = 0.0f;
            float pa[8], pb[8];
#pragma unroll
            for (int k = 0; k < 16; k++) {
#pragma unroll
                for (int a = jb+1; a < 8; a++) pa[a] = A[(ty + 16*a)*PAD + jb*16 + k];
#pragma unroll
                for (int b = jb+1; b < 8; b++) pb[b] = A[(tx + 16*b)*PAD + jb*16 + k];
#pragma unroll
                for (int a = jb+1; a < 8; a++)
#pragma unroll
                    for (int b = jb+1; b <= a; b++) tacc[a][b] += pa[a] * pb[b];
            }
#pragma unroll
            for (int a = jb+1; a < 8; a++)
#pragma unroll
                for (int b = jb+1; b <= a; b++)
                    A[(ty + 16*a)*PAD + tx + 16*b] -= tacc[a][b];
            __syncthreads();
        }
    }
}

__device__ __noinline__ void trsm_blocked(float* A, const float* dinv,
                                          float* scratch, int tid) {
    const int warp = tid >> 5;
    const int lane = tid & 31;
    const int c = lane & 15, rh = lane >> 4;
#pragma unroll
    for (int ib = 0; ib < 8; ib++) {
        if (warp == 7 && lane < 16) {
            const float* Ld = A + (ib*16)*PAD + ib*16;
            float dv[16], t[16];
#pragma unroll
            for (int r = 0; r < 16; r++) dv[r] = dinv[ib*16 + r];
#pragma unroll
            for (int r = 0; r < 16; r++) t[r] = (r == c) ? 1.0f : 0.0f;
#pragma unroll
            for (int r = 0; r < 16; r++) {
                float x = t[r] * dv[r];
                t[r] = x;
#pragma unroll
                for (int k = r + 1; k < 16; k++)
                    t[k] = fmaf(-x, Ld[k*PAD + r], t[k]);
            }
#pragma unroll
            for (int r = 0; r < 16; r++) scratch[8*272 + r*17 + c] = t[r];
        }
        float acc[8];
        if (warp < ib) {
#pragma unroll
            for (int q = 0; q < 8; q++) acc[q] = 0.0f;
            for (int kb = warp; kb < ib; kb++) {
#pragma unroll
                for (int k = 0; k < 16; k++) {
                    float xv = A[(kb*16 + k)*PAD + warp*16 + c];
#pragma unroll
                    for (int q = 0; q < 8; q++)
                        acc[q] -= A[(ib*16 + rh*8 + q)*PAD + kb*16 + k] * xv;
                }
            }
#pragma unroll
            for (int q = 0; q < 8; q++)
                scratch[warp*272 + (rh*8 + q)*17 + c] = acc[q];
        }
        __syncthreads();
        if (warp < ib) {
            const float* Dv = scratch + 8*272;
            const float* T  = scratch + warp*272;
#pragma unroll
            for (int q = 0; q < 8; q++) {
                const int r = rh*8 + q;
                float t = 0.0f;
#pragma unroll
                for (int k = 0; k < 16; k++) t += Dv[r*17 + k] * T[k*17 + c];
                A[(ib*16 + r)*PAD + warp*16 + c] = t;
            }
        }
        if (warp == 7 && lane < 16) {
            const float* Dv = scratch + 8*272;
#pragma unroll
            for (int r = 0; r < 16; r++)
                A[(ib*16 + r)*PAD + ib*16 + c] = Dv[r*17 + c];
        }
        __syncthreads();
    }
}

__global__ __launch_bounds__(256, 2)
void k1_factor(const float* __restrict__ U,
               const float* __restrict__ pmu,
               const float* __restrict__ plogprec,
               const float* __restrict__ eps) {
    extern __shared__ unsigned char smraw[];
    char* sm = (char*)smraw;
    const uint32_t smb = s2u(sm);

    float* A    = (float*)(sm + OFF_A);
    float* P    = (float*)(sm + OFF_P);
    float* sqlp = (float*)(sm + OFF_SQLP);
    float* smu  = (float*)(sm + OFF_SMU);
    float* utlv = (float*)(sm + OFF_UTLV);
    float* dinv = (float*)(sm + OFF_DINV);
    float* qmu  = (float*)(sm + OFF_QMU);
    float* epsv = (float*)(sm + OFF_EPSV);
    float* red  = (float*)(sm + OFF_RED);

    const int so = blockIdx.x;
    const int s = so >> 7;
    const int o = so & 127;
    const int tid = threadIdx.x;
    const int wid = tid >> 5;
    const int lane = tid & 31;

    if (tid < 128) {
        float l = expf(plogprec[o*MM + tid]);
        float sq = sqrtf(l);
        sqlp[tid] = sq;
        smu[tid]  = sq * pmu[o*MM + tid];
        epsv[tid] = eps[(s*OO + o)*DD + tid];
        utlv[tid] = 0.0f;
    }
    __syncthreads();

    // ---- tile lists: 72 lower tiles (rb, jb <= 2rb+1), 9/warp ----
    int rbv[9], jbv[9];
    {
        int t = 0, idx = 0;
        for (int rb = 0; rb < 8; rb++)
            for (int jb = 0; jb <= 2*rb + 1; jb++) {
                if ((idx & 7) == wid) { rbv[t] = rb; jbv[t] = jb; t++; }
                idx++;
            }
    }
    const int aRow  = lane & 15;
    const int aColH = (lane >> 4) * 8;
    const int bRow  = lane & 7;
    const int bCol  = (lane >> 3) * 8;

    float cc[9][4];
#pragma unroll
    for (int t = 0; t < 9; t++)
#pragma unroll
        for (int q = 0; q < 4; q++) cc[t][q] = 0.f;

    const int pfd = tid & 127;          // d index of this thread's staging slots
    const int pfm = tid >> 7;           // base ml (0 or 1); slots ml = pfm + 2*it

    // ============ Gram = P~^T P~  (32-m chunks, prefetch, prmt pass2) ============
    float pf[16];
    // preload chunk 0
#pragma unroll
    for (int it = 0; it < 16; it++) {
        int ml = pfm + 2*it;
        pf[it] = U[((size_t)s*MM + ml)*DD + pfd];
    }
#pragma unroll
    for (int c = 0; c < 4; c++) {
        // stage P (scaled relu) from prefetched regs
#pragma unroll
        for (int it = 0; it < 16; it++) {
            int ml = pfm + 2*it;
            P[ml*P_STRIDE + pfd] = sqlp[c*32 + ml] * fmaxf(pf[it], 0.f);
        }
        __syncthreads();
        // utlv partial + convert P -> SB0 (interleaved h,m along doubled-k)
        if (tid < 128) {
            float a = utlv[tid];
#pragma unroll
            for (int ml = 0; ml < 32; ml++)
                a = fmaf(smu[c*32 + ml], P[ml*P_STRIDE + tid], a);
            utlv[tid] = a;
        }
#pragma unroll
        for (int it = 0; it < 16; it++) {
            int idx = tid + it*256;
            int ml = idx & 31, d = idx >> 5;
            float v = P[ml*P_STRIDE + d];
            __nv_bfloat16 h = __float2bfloat16(v);
            __nv_bfloat16 m2 = __float2bfloat16(v - __bfloat162float(h));
            *(uint32_t*)(sm + OFF_SB0 + d*SB_STRIDE_B + ml*4) = pack_bf2(h, m2);
        }
        __syncthreads();
        // prefetch next chunk + mma
        if (c < 3) {
#pragma unroll
            for (int it = 0; it < 16; it++) {
                int ml = pfm + 2*it;
                pf[it] = U[((size_t)s*MM + (c+1)*32 + ml)*DD + pfd];
            }
        }
#pragma unroll
        for (int t = 0; t < 9; t++) {
            uint32_t aBase = smb + OFF_SB0 + (uint32_t)(rbv[t]*16 + aRow)*SB_STRIDE_B + aColH*2;
            uint32_t bBase = smb + OFF_SB0 + (uint32_t)(jbv[t]*8 + bRow)*SB_STRIDE_B + bCol*2;
#pragma unroll
            for (int g = 0; g < 2; g++) {
                uint32_t b0,b1,b2,b3;
                ldsm_x4(bBase + g*64, b0,b1,b2,b3);
                uint32_t s0 = swap16(b0), s1 = swap16(b1), s2 = swap16(b2), s3 = swap16(b3);
                uint32_t a0,a1,a2,a3;
                ldsm_x4(aBase + (2*g)*32, a0,a1,a2,a3);
                mma16816(cc[t][0],cc[t][1],cc[t][2],cc[t][3], a0,a1,a2,a3, b0,b1);
                mma16816(cc[t][0],cc[t][1],cc[t][2],cc[t][3], a0,a1,a2,a3, s0,s1);
                ldsm_x4(aBase + (2*g+1)*32, a0,a1,a2,a3);
                mma16816(cc[t][0],cc[t][1],cc[t][2],cc[t][3], a0,a1,a2,a3, b2,b3);
                mma16816(cc[t][0],cc[t][1],cc[t][2],cc[t][3], a0,a1,a2,a3, s2,s3);
            }
        }
        __syncthreads();
    }
    // store Gram + I
    {
        const int g = lane >> 2, tc = (lane & 3) * 2;
#pragma unroll
        for (int t = 0; t < 9; t++) {
            int i0 = rbv[t]*16 + g, j0 = jbv[t]*8 + tc;
            A[i0*PAD + j0]       = cc[t][0] + (i0 == j0     ? 1.f : 0.f);
            A[i0*PAD + j0 + 1]   = cc[t][1] + (i0 == j0 + 1 ? 1.f : 0.f);
            A[(i0+8)*PAD + j0]   = cc[t][2] + (i0+8 == j0   ? 1.f : 0.f);
            A[(i0+8)*PAD + j0+1] = cc[t][3] + (i0+8 == j0+1 ? 1.f : 0.f);
        }
    }
    __syncthreads();

    // ---- L = chol(A); X = L^{-1} ----
    chol_blocked(A, dinv, tid);
    trsm_blocked(A, dinv, (float*)(sm + OFF_SCRATCH), tid);

    // ============ q_cov = X^T X  (32-k chunks, staged directly from A) ============
#pragma unroll
    for (int t = 0; t < 9; t++)
#pragma unroll
        for (int q = 0; q < 4; q++) cc[t][q] = 0.f;

#pragma unroll
    for (int c = 0; c < 4; c++) {
        // stage: SB0[i][2kl] = (h,m) of X[k=32c+kl][i]; conflict-free both sides
#pragma unroll
        for (int it = 0; it < 16; it++) {
            int idx = tid + it*256;
            int kl = idx & 31, i = idx >> 5;
            int k = c*32 + kl;
            float v = (i <= k) ? A[k*PAD + i] : 0.f;
            __nv_bfloat16 h = __float2bfloat16(v);
            __nv_bfloat16 m2 = __float2bfloat16(v - __bfloat162float(h));
            *(uint32_t*)(sm + OFF_SB0 + i*SB_STRIDE_B + kl*4) = pack_bf2(h, m2);
        }
        __syncthreads();
        const int rbmax = 2*c + 1;
#pragma unroll
        for (int t = 0; t < 9; t++) {
            if (rbv[t] > rbmax) continue;
            uint32_t aBase = smb + OFF_SB0 + (uint32_t)(rbv[t]*16 + aRow)*SB_STRIDE_B + aColH*2;
            uint32_t bBase = smb + OFF_SB0 + (uint32_t)(jbv[t]*8 + bRow)*SB_STRIDE_B + bCol*2;
#pragma unroll
            for (int g = 0; g < 2; g++) {
                uint32_t b0,b1,b2,b3;
                ldsm_x4(bBase + g*64, b0,b1,b2,b3);
                uint32_t s0 = swap16(b0), s1 = swap16(b1), s2 = swap16(b2), s3 = swap16(b3);
                uint32_t a0,a1,a2,a3;
                ldsm_x4(aBase + (2*g)*32, a0,a1,a2,a3);
                mma16816(cc[t][0],cc[t][1],cc[t][2],cc[t][3], a0,a1,a2,a3, b0,b1);
                mma16816(cc[t][0],cc[t][1],cc[t][2],cc[t][3], a0,a1,a2,a3, s0,s1);
                ldsm_x4(aBase + (2*g+1)*32, a0,a1,a2,a3);
                mma16816(cc[t][0],cc[t][1],cc[t][2],cc[t][3], a0,a1,a2,a3, b2,b3);
                mma16816(cc[t][0],cc[t][1],cc[t][2],cc[t][3], a0,a1,a2,a3, s2,s3);
            }
        }
        __syncthreads();
    }
    // store q_cov (direct + mirror for strictly-off-diagonal tiles)
    {
        const int g = lane >> 2, tc = (lane & 3) * 2;
#pragma unroll
        for (int t = 0; t < 9; t++) {
            int i0 = rbv[t]*16 + g, j0 = jbv[t]*8 + tc;
            A[i0*PAD + j0]       = cc[t][0];
            A[i0*PAD + j0 + 1]   = cc[t][1];
            A[(i0+8)*PAD + j0]   = cc[t][2];
            A[(i0+8)*PAD + j0+1] = cc[t][3];
            if ((jbv[t] >> 1) != rbv[t]) {
                A[j0*PAD + i0]       = cc[t][0];
                A[(j0+1)*PAD + i0]   = cc[t][1];
                A[j0*PAD + i0 + 8]   = cc[t][2];
                A[(j0+1)*PAD + i0+8] = cc[t][3];
            }
        }
    }
    __syncthreads();

    // ---- q_mu = q_cov @ utlv ----
    if (tid < 128) {
        float a = 0.0f;
#pragma unroll 8
        for (int e = 0; e < DD; e++) a += A[tid*PAD + e] * utlv[e];
        qmu[tid] = a;
    }
    __syncthreads();

    if (tid < 128) red[tid] = A[tid*PAD + tid] + qmu[tid]*qmu[tid];
    __syncthreads();
    float trmu = 0.0f;
    if (tid < 32) {
        float p = red[tid] + red[tid+32] + red[tid+64] + red[tid+96];
#pragma unroll
        for (int off = 16; off > 0; off >>= 1)
            p += __shfl_xor_sync(0xFFFFFFFFu, p, off);
        trmu = p;
    }
    __syncthreads();

    // ---- Lcov = chol(q_cov) ----
    chol_blocked(A, dinv, tid);

    if (tid < 128) red[tid] = logf(A[tid*PAD + tid]);
    __syncthreads();

    // ---- w = q_mu + Lcov @ eps ; KL ----
    if (tid < 128) {
        float a = qmu[tid];
        for (int e = 0; e <= tid; e++)
            a += A[tid*PAD + e] * epsv[e];
        g_w[(s*OO + o)*DD + tid] = a;
    }
    if (tid < 32) {
        float p = red[tid] + red[tid+32] + red[tid+64] + red[tid+96];
#pragma unroll
        for (int off = 16; off > 0; off >>= 1)
            p += __shfl_xor_sync(0xFFFFFFFFu, p, off);
        if (tid == 0)
            g_klso[so] = 0.5f * (trmu - (float)DD) - p;
    }
}

// ---- k2: F_out / U_out GEMMs, float4-over-k ----
#define KP 36
__global__ __launch_bounds__(256, 2)
void k2_gemm(const float* __restrict__ F, const float* __restrict__ U,
             float* __restrict__ outF, float* __restrict__ outU) {
    __shared__ float At[128*KP];
    __shared__ float Bt[128*KP];
    const int b = blockIdx.x;
    const int tid = threadIdx.x;
    const int ty = tid >> 4, tx = tid & 15;

    int s;
    const float* Ag;
    float* Cg;
    if (b < SS * (NN/128)) {
        s = b >> 5;
        int nt = b & 31;
        Ag = F + (size_t)(s*NN + nt*128) * DD;
        Cg = outF + (size_t)(s*NN + nt*128) * OO;
    } else {
        s = b - SS * (NN/128);
        Ag = U + (size_t)(s*MM) * DD;
        Cg = outU + (size_t)(s*MM) * OO;
    }
    const float* W = g_w + (size_t)s * OO * DD;

    float acc[8][8];
#pragma unroll
    for (int a = 0; a < 8; a++)
#pragma unroll
        for (int c = 0; c < 8; c++) acc[a][c] = 0.0f;

    for (int kb = 0; kb < DD; kb += 32) {
        __syncthreads();
        for (int idx = tid; idx < 128*8; idx += 256) {
            int r = idx >> 3, c4 = idx & 7;
            float4 v = *(const float4*)&Ag[r*DD + kb + 4*c4];
            v.x = fmaxf(v.x, 0.f); v.y = fmaxf(v.y, 0.f);
            v.z = fmaxf(v.z, 0.f); v.w = fmaxf(v.w, 0.f);
            *(float4*)&At[r*KP + 4*c4] = v;
            *(float4*)&Bt[r*KP + 4*c4] = *(const float4*)&W[r*DD + kb + 4*c4];
        }
        __syncthreads();
#pragma unroll
        for (int k4 = 0; k4 < 8; k4++) {
            float4 bv[8];
#pragma unroll
            for (int c = 0; c < 8; c++)
                bv[c] = *(const float4*)&Bt[(tx + 16*c)*KP + 4*k4];
#pragma unroll
            for (int a = 0; a < 8; a++) {
                float4 av = *(const float4*)&At[(ty + 16*a)*KP + 4*k4];
#pragma unroll
                for (int c = 0; c < 8; c++) {
                    acc[a][c] += av.x * bv[c].x;
                    acc[a][c] += av.y * bv[c].y;
                    acc[a][c] += av.z * bv[c].z;
                    acc[a][c] += av.w * bv[c].w;
                }
            }
        }
    }
#pragma unroll
    for (int a = 0; a < 8; a++)
#pragma unroll
        for (int c = 0; c < 8; c++)
            Cg[(ty + 16*a)*OO + tx + 16*c] = acc[a][c];
}

__global__ void k3_kl(float* __restrict__ kl) {
    int s = threadIdx.x;
    if (s < SS) {
        float a = 0.0f;
        for (int o = 0; o < OO; o++) a += g_klso[s*OO + o];
        kl[s] = a;
    }
}

extern "C" void kernel_launch(void* const* d_in, const int* in_sizes, int n_in,
                              void* d_out, int out_size) {
    const float* F        = (const float*)d_in[0];
    const float* U        = (const float*)d_in[1];
    const float* pmu      = (const float*)d_in[2];
    const float* plogprec = (const float*)d_in[3];
    const float* eps      = (const float*)d_in[4];

    float* out  = (float*)d_out;
    float* outF = out;
    float* outU = outF + (size_t)SS*NN*OO;
    float* outK = outU + (size_t)SS*MM*OO;

    cudaFuncSetAttribute(k1_factor, cudaFuncAttributeMaxDynamicSharedMemorySize,
                         SMEM_DYN);

    k1_factor<<<SS*OO, 256, SMEM_DYN>>>(U, pmu, plogprec, eps);
    k2_gemm<<<SS*(NN/128) + SS, 256>>>(F, U, outF, outU);
    k3_kl<<<1, 32>>>(outK);
}